// round 1
// baseline (speedup 1.0000x reference)
#include <cuda_runtime.h>
#include <cuda_bf16.h>
#include <cstdint>

// Problem constants
#define N_TOK   4096
#define D_MODEL 1024
#define D_HID   32768
#define TOPK    128
#define EPS     1e-5f

// ---------------- scratch (device globals; no allocs allowed) ----------------
__device__ float g_xn[(size_t)N_TOK * D_MODEL];           // 16 MB  normalized input
__device__ float g_pre[(size_t)N_TOK * D_HID];            // 512 MB pre-activations
__device__ float g_mu[N_TOK];
__device__ float g_sd[N_TOK];
__device__ float g_tv[(size_t)N_TOK * TOPK];
__device__ int   g_ti[(size_t)N_TOK * TOPK];

// ---------------- LayerNorm (torch-style: unbiased std, /(std+eps)) ----------
__device__ __forceinline__ float block_reduce_sum256(float v, float* red) {
    #pragma unroll
    for (int o = 16; o > 0; o >>= 1) v += __shfl_xor_sync(0xffffffffu, v, o);
    int w = threadIdx.x >> 5;
    if ((threadIdx.x & 31) == 0) red[w] = v;
    __syncthreads();
    float r = (threadIdx.x < 8) ? red[threadIdx.x] : 0.f;
    if (threadIdx.x < 32) {
        #pragma unroll
        for (int o = 4; o > 0; o >>= 1) r += __shfl_xor_sync(0xffffffffu, r, o);
        if (threadIdx.x == 0) red[0] = r;
    }
    __syncthreads();
    float out = red[0];
    __syncthreads();
    return out;
}

__global__ __launch_bounds__(256) void ln_kernel(const float* __restrict__ x,
                                                 const float* __restrict__ b_pre) {
    __shared__ float sx[D_MODEL];
    __shared__ float red[32];
    const int row = blockIdx.x;
    const int t = threadIdx.x;
    const float* xr = x + (size_t)row * D_MODEL;

    float sum = 0.f;
    #pragma unroll
    for (int q = 0; q < 4; q++) {
        float f = xr[t + q * 256];
        sx[t + q * 256] = f;
        sum += f;
    }
    float total = block_reduce_sum256(sum, red);
    float m = total * (1.0f / D_MODEL);

    float sq = 0.f;
    #pragma unroll
    for (int q = 0; q < 4; q++) {
        float c = sx[t + q * 256] - m;
        sq += c * c;
    }
    float sstot = block_reduce_sum256(sq, red);
    float sd = sqrtf(sstot * (1.0f / (D_MODEL - 1)));
    float inv = 1.0f / (sd + EPS);

    #pragma unroll
    for (int q = 0; q < 4; q++) {
        int col = t + q * 256;
        g_xn[(size_t)row * D_MODEL + col] = (sx[col] - m) * inv - b_pre[col];
    }
    if (t == 0) { g_mu[row] = m; g_sd[row] = sd; }
}

// ---------------- fp32 SIMT GEMM: pre = xn @ w_enc + b_enc -------------------
// A: [N_TOK, D_MODEL] row-major, B: [D_MODEL, D_HID] row-major, C: [N_TOK, D_HID]
#define TM 128
#define TN 128
#define TK 16

__global__ __launch_bounds__(256, 2) void enc_gemm_kernel(const float* __restrict__ B,
                                                          const float* __restrict__ bias) {
    __shared__ float As[TK][TM];   // 8 KB
    __shared__ float Bs[TK][TN];   // 8 KB
    const int bm = blockIdx.y * TM;
    const int bn = blockIdx.x * TN;
    const int t = threadIdx.x;
    const int tx = t & 15;         // col group
    const int ty = t >> 4;         // row group

    float acc[8][8];
    #pragma unroll
    for (int i = 0; i < 8; i++)
        #pragma unroll
        for (int j = 0; j < 8; j++) acc[i][j] = 0.f;

    const float* A = g_xn;

    for (int k0 = 0; k0 < D_MODEL; k0 += TK) {
        // load A tile: 128 rows x 16 k, transposed into As[k][row]
        #pragma unroll
        for (int l = 0; l < 2; l++) {
            int i = t + l * 256;           // [0,512)
            int row = i >> 2;
            int kq = (i & 3) * 4;
            float4 v = *reinterpret_cast<const float4*>(
                &A[(size_t)(bm + row) * D_MODEL + k0 + kq]);
            As[kq + 0][row] = v.x;
            As[kq + 1][row] = v.y;
            As[kq + 2][row] = v.z;
            As[kq + 3][row] = v.w;
        }
        // load B tile: 16 k x 128 cols, direct
        #pragma unroll
        for (int l = 0; l < 2; l++) {
            int i = t + l * 256;
            int kk = i >> 5;
            int hq = (i & 31) * 4;
            float4 v = *reinterpret_cast<const float4*>(
                &B[(size_t)(k0 + kk) * D_HID + bn + hq]);
            *reinterpret_cast<float4*>(&Bs[kk][hq]) = v;
        }
        __syncthreads();

        #pragma unroll
        for (int kk = 0; kk < TK; kk++) {
            float a[8], b[8];
            *reinterpret_cast<float4*>(&a[0]) = *reinterpret_cast<const float4*>(&As[kk][ty * 8]);
            *reinterpret_cast<float4*>(&a[4]) = *reinterpret_cast<const float4*>(&As[kk][ty * 8 + 4]);
            *reinterpret_cast<float4*>(&b[0]) = *reinterpret_cast<const float4*>(&Bs[kk][tx * 8]);
            *reinterpret_cast<float4*>(&b[4]) = *reinterpret_cast<const float4*>(&Bs[kk][tx * 8 + 4]);
            #pragma unroll
            for (int i = 0; i < 8; i++)
                #pragma unroll
                for (int j = 0; j < 8; j++)
                    acc[i][j] += a[i] * b[j];
        }
        __syncthreads();
    }

    // epilogue: add bias, store
    #pragma unroll
    for (int i = 0; i < 8; i++) {
        int row = bm + ty * 8 + i;
        #pragma unroll
        for (int j = 0; j < 8; j += 4) {
            int col = bn + tx * 8 + j;
            float4 v;
            v.x = acc[i][j + 0] + bias[col + 0];
            v.y = acc[i][j + 1] + bias[col + 1];
            v.z = acc[i][j + 2] + bias[col + 2];
            v.w = acc[i][j + 3] + bias[col + 3];
            *reinterpret_cast<float4*>(&g_pre[(size_t)row * D_HID + col]) = v;
        }
    }
}

// ---------------- top-k (k=128) radix select per row --------------------------
// One block per row. Row keys cached in dynamic SMEM (128 KB), 4x 8-bit MSB passes.
__global__ __launch_bounds__(256) void topk_kernel() {
    extern __shared__ uint32_t u[];  // D_HID keys
    __shared__ int hist[256];
    __shared__ uint32_t s_prefix;
    __shared__ int s_remaining, s_outpos, s_tiecnt;

    const int row = blockIdx.x;
    const int t = threadIdx.x;
    const float* p = g_pre + (size_t)row * D_HID;

    for (int i = t; i < D_HID; i += 256) {
        uint32_t b = __float_as_uint(p[i]);
        u[i] = (b & 0x80000000u) ? ~b : (b | 0x80000000u);  // monotonic key
    }
    if (t == 0) { s_prefix = 0; s_remaining = TOPK; s_outpos = 0; s_tiecnt = 0; }
    __syncthreads();

    for (int byte = 3; byte >= 0; byte--) {
        hist[t] = 0;                // blockDim == 256
        __syncthreads();
        const uint32_t prefix = s_prefix;
        const int shift = byte * 8;
        const uint32_t himask = (byte == 3) ? 0u : (0xFFFFFFFFu << (shift + 8));
        for (int i = t; i < D_HID; i += 256) {
            uint32_t v = u[i];
            if ((v & himask) == (prefix & himask))
                atomicAdd(&hist[(v >> shift) & 255], 1);
        }
        __syncthreads();
        if (t == 0) {
            int rem = s_remaining;
            int b = 255;
            for (; b > 0; b--) {
                if (hist[b] >= rem) break;
                rem -= hist[b];
            }
            s_prefix = prefix | ((uint32_t)b << shift);
            s_remaining = rem;
        }
        __syncthreads();
    }

    const uint32_t T = s_prefix;
    const int tieQuota = s_remaining;
    for (int i = t; i < D_HID; i += 256) {
        uint32_t v = u[i];
        bool take = false;
        if (v > T) take = true;
        else if (v == T) {
            if (atomicAdd(&s_tiecnt, 1) < tieQuota) take = true;
        }
        if (take) {
            int pos = atomicAdd(&s_outpos, 1);
            g_tv[(size_t)row * TOPK + pos] = fmaxf(p[i], 0.0f);  // relu
            g_ti[(size_t)row * TOPK + pos] = i;
        }
    }
}

// ---------------- sparse decode + de-normalize -------------------------------
__global__ __launch_bounds__(256) void decode_kernel(const float* __restrict__ w_dec,
                                                     const float* __restrict__ b_pre,
                                                     float* __restrict__ out) {
    __shared__ float sval[TOPK];
    __shared__ int   sidx[TOPK];
    const int row = blockIdx.x;
    const int t = threadIdx.x;
    if (t < TOPK) {
        sval[t] = g_tv[(size_t)row * TOPK + t];
        sidx[t] = g_ti[(size_t)row * TOPK + t];
    }
    __syncthreads();

    float acc0 = 0.f, acc1 = 0.f, acc2 = 0.f, acc3 = 0.f;
    #pragma unroll 4
    for (int j = 0; j < TOPK; j++) {
        const float v = sval[j];
        const float* wr = w_dec + (size_t)sidx[j] * D_MODEL;
        acc0 += v * __ldg(&wr[t]);
        acc1 += v * __ldg(&wr[t + 256]);
        acc2 += v * __ldg(&wr[t + 512]);
        acc3 += v * __ldg(&wr[t + 768]);
    }
    const float m = g_mu[row], s = g_sd[row];
    float* o = out + (size_t)row * D_MODEL;
    o[t]       = (acc0 + b_pre[t])       * s + m;
    o[t + 256] = (acc1 + b_pre[t + 256]) * s + m;
    o[t + 512] = (acc2 + b_pre[t + 512]) * s + m;
    o[t + 768] = (acc3 + b_pre[t + 768]) * s + m;
}

// ---------------- launch ------------------------------------------------------
extern "C" void kernel_launch(void* const* d_in, const int* in_sizes, int n_in,
                              void* d_out, int out_size) {
    const float* x     = (const float*)d_in[0];
    const float* w_enc = (const float*)d_in[1];
    const float* w_dec = (const float*)d_in[2];
    const float* b_enc = (const float*)d_in[3];
    const float* b_pre = (const float*)d_in[4];
    float* out = (float*)d_out;

    // 1. LayerNorm
    ln_kernel<<<N_TOK, 256>>>(x, b_pre);

    // 2. Encoder GEMM (fp32 exact — top-k boundary spacing ~2.7e-4 forbids tf32)
    dim3 ggrid(D_HID / TN, N_TOK / TM);
    enc_gemm_kernel<<<ggrid, 256>>>(w_enc, b_enc);

    // 3. Top-128 radix select per row (row cached in 128 KB dynamic SMEM)
    static_assert(D_HID * sizeof(uint32_t) == 131072, "smem size");
    cudaFuncSetAttribute(topk_kernel, cudaFuncAttributeMaxDynamicSharedMemorySize,
                         D_HID * (int)sizeof(uint32_t));
    topk_kernel<<<N_TOK, 256, D_HID * sizeof(uint32_t)>>>();

    // 4. Sparse decode + un-normalize
    decode_kernel<<<N_TOK, 256>>>(w_dec, b_pre, out);
}

// round 5
// speedup vs baseline: 2.5565x; 2.5565x over previous
#include <cuda_runtime.h>
#include <cuda_fp16.h>
#include <cstdint>

// Problem constants
#define N_TOK   4096
#define D_MODEL 1024
#define D_HID   32768
#define TOPK    128
#define EPS     1e-5f
#define CAND_MAX 256
#define MARGIN  4e-3f

// GEMM tiling
#define TM   128
#define TN   128
#define TKC  64                          // k-halfs per chunk (128B rows)
#define NCHUNK (D_MODEL / TKC)           // 16
#define STAGE_BYTES 32768                // ah(16K) + bh(16K)
#define GEMM_SMEM (2 * STAGE_BYTES)      // 64 KB

// ---------------- scratch (device globals; no allocs allowed) ----------------
__device__ __half g_ah[(size_t)N_TOK * D_MODEL];           // xn fp16
__device__ float  g_xn[(size_t)N_TOK * D_MODEL];           // xn fp32 (rescue)
__device__ __half g_bh[(size_t)D_HID * D_MODEL];           // (256*w_enc)^T fp16
__device__ float  g_bt[(size_t)D_HID * D_MODEL];           // w_enc^T fp32 (rescue)
__device__ float g_pre[(size_t)N_TOK * D_HID];             // 512 MB approx pre-acts
__device__ float g_mu[N_TOK];
__device__ float g_sd[N_TOK];
__device__ int   g_ci[(size_t)N_TOK * CAND_MAX];           // candidate indices
__device__ int   g_cn[N_TOK];                              // candidate counts
__device__ float g_tv[(size_t)N_TOK * TOPK];
__device__ int   g_ti[(size_t)N_TOK * TOPK];

// ---------------- PTX helpers -------------------------------------------------
__device__ __forceinline__ uint32_t smem_u32(const void* p) {
    uint32_t a;
    asm("{ .reg .u64 t; cvta.to.shared.u64 t, %1; cvt.u32.u64 %0, t; }" : "=r"(a) : "l"(p));
    return a;
}
__device__ __forceinline__ void cp16(uint32_t dst, const void* src) {
    asm volatile("cp.async.cg.shared.global [%0], [%1], 16;" :: "r"(dst), "l"(src) : "memory");
}
#define CP_COMMIT()   asm volatile("cp.async.commit_group;" ::: "memory")
#define CP_WAIT(n)    asm volatile("cp.async.wait_group %0;" :: "n"(n) : "memory")

#define LDSM4(R0, R1, R2, R3, A)                                                  \
    asm volatile("ldmatrix.sync.aligned.m8n8.x4.shared.b16 {%0,%1,%2,%3}, [%4];"  \
        : "=r"(R0), "=r"(R1), "=r"(R2), "=r"(R3) : "r"(A))

#define MMA16816(D, A, B0, B1)                                                    \
    asm volatile("mma.sync.aligned.m16n8k16.row.col.f32.f16.f16.f32 "             \
        "{%0,%1,%2,%3}, {%4,%5,%6,%7}, {%8,%9}, {%0,%1,%2,%3};"                   \
        : "+f"((D)[0]), "+f"((D)[1]), "+f"((D)[2]), "+f"((D)[3])                   \
        : "r"((A)[0]), "r"((A)[1]), "r"((A)[2]), "r"((A)[3]), "r"(B0), "r"(B1))

// ---------------- LayerNorm ----------------------------------------------------
__device__ __forceinline__ float block_reduce_sum256(float v, float* red) {
    #pragma unroll
    for (int o = 16; o > 0; o >>= 1) v += __shfl_xor_sync(0xffffffffu, v, o);
    int w = threadIdx.x >> 5;
    if ((threadIdx.x & 31) == 0) red[w] = v;
    __syncthreads();
    float r = (threadIdx.x < 8) ? red[threadIdx.x] : 0.f;
    if (threadIdx.x < 32) {
        #pragma unroll
        for (int o = 4; o > 0; o >>= 1) r += __shfl_xor_sync(0xffffffffu, r, o);
        if (threadIdx.x == 0) red[0] = r;
    }
    __syncthreads();
    float out = red[0];
    __syncthreads();
    return out;
}

__global__ __launch_bounds__(256) void ln_kernel(const float* __restrict__ x,
                                                 const float* __restrict__ b_pre) {
    __shared__ float sx[D_MODEL];
    __shared__ float red[32];
    const int row = blockIdx.x;
    const int t = threadIdx.x;
    const float* xr = x + (size_t)row * D_MODEL;

    float sum = 0.f;
    #pragma unroll
    for (int q = 0; q < 4; q++) { float f = xr[t + q * 256]; sx[t + q * 256] = f; sum += f; }
    float m = block_reduce_sum256(sum, red) * (1.0f / D_MODEL);

    float sq = 0.f;
    #pragma unroll
    for (int q = 0; q < 4; q++) { float c = sx[t + q * 256] - m; sq += c * c; }
    float sd = sqrtf(block_reduce_sum256(sq, red) * (1.0f / (D_MODEL - 1)));
    float inv = 1.0f / (sd + EPS);

    #pragma unroll
    for (int q = 0; q < 4; q++) {
        int col = t + q * 256;
        float v = (sx[col] - m) * inv - b_pre[col];
        size_t idx = (size_t)row * D_MODEL + col;
        g_xn[idx] = v;
        g_ah[idx] = __float2half_rn(v);
    }
    if (t == 0) { g_mu[row] = m; g_sd[row] = sd; }
}

// ---------------- transpose: w_enc -> [D_HID, D_MODEL] fp32 + fp16(x256) ------
__global__ __launch_bounds__(256) void transpose_split(const float* __restrict__ w) {
    __shared__ float tile[32][33];
    const int n0 = blockIdx.x * 32, k0 = blockIdx.y * 32;
    const int tx = threadIdx.x, ty = threadIdx.y;
    #pragma unroll
    for (int i = 0; i < 32; i += 8)
        tile[ty + i][tx] = w[(size_t)(k0 + ty + i) * D_HID + n0 + tx];
    __syncthreads();
    #pragma unroll
    for (int i = 0; i < 32; i += 8) {
        float v = tile[tx][ty + i];
        size_t idx = (size_t)(n0 + ty + i) * D_MODEL + k0 + tx;
        g_bt[idx] = v;
        g_bh[idx] = __float2half_rn(v * 256.0f);   // scale so small entries stay normal
    }
}

// ---------------- HMMA GEMM (approx, single fp16 product) ---------------------
// A tiles [128 x 64] halfs (row=m, 128B/row), B tiles [128 x 64] (row=n),
// XOR swizzle: 16B chunk c at row r stored at c ^ (r & 7).
__device__ __forceinline__ void load_chunk(uint32_t stage, int bm, int bn, int k0, int t) {
    #pragma unroll
    for (int i = 0; i < 4; i++) {
        int g = t + i * 256;                // 0..1023
        int row = g >> 3, ch = g & 7;
        uint32_t dst = stage + (uint32_t)row * 128 + (uint32_t)((ch ^ (row & 7)) * 16);
        cp16(dst,         g_ah + (size_t)(bm + row) * D_MODEL + k0 + ch * 8);
        cp16(dst + 16384, g_bh + (size_t)(bn + row) * D_MODEL + k0 + ch * 8);
    }
}

__global__ __launch_bounds__(256, 1) void enc_gemm_mma(const float* __restrict__ bias) {
    extern __shared__ __align__(1024) char smem[];
    const uint32_t sb = smem_u32(smem);
    const int t = threadIdx.x;
    const int wid = t >> 5, lane = t & 31;
    const int wm = wid >> 1, wn = wid & 1;      // 4x2 warps, warp tile 32x64
    const int bm = blockIdx.x * TM;
    const int bn = blockIdx.y * TN;

    float acc[2][8][4];
    #pragma unroll
    for (int i = 0; i < 2; i++)
        #pragma unroll
        for (int j = 0; j < 8; j++)
            #pragma unroll
            for (int q = 0; q < 4; q++) acc[i][j][q] = 0.f;

    const int laneA = lane & 15;
    const int hiA   = lane >> 4;
    const int rBoff = (lane & 7) + ((lane >> 4) << 3);
    const int hiB   = (lane >> 3) & 1;

    load_chunk(sb, bm, bn, 0, t);
    CP_COMMIT();

    for (int c = 0; c < NCHUNK; c++) {
        if (c + 1 < NCHUNK) {
            load_chunk(sb + (uint32_t)((c + 1) & 1) * STAGE_BYTES, bm, bn, (c + 1) * TKC, t);
            CP_COMMIT();
            CP_WAIT(1);
        } else {
            CP_WAIT(0);
        }
        __syncthreads();

        const uint32_t base = sb + (uint32_t)(c & 1) * STAGE_BYTES;
        const uint32_t Ah = base, Bh = base + 16384;

        #pragma unroll
        for (int ks = 0; ks < 4; ks++) {
            const int c0 = ks * 2;
            uint32_t aH[2][4], bH[8][2];
            #pragma unroll
            for (int tm = 0; tm < 2; tm++) {
                int r = wm * 32 + tm * 16 + laneA;
                uint32_t off = (uint32_t)r * 128 + (uint32_t)((((c0 + hiA) ^ (r & 7))) * 16);
                LDSM4(aH[tm][0], aH[tm][1], aH[tm][2], aH[tm][3], Ah + off);
            }
            #pragma unroll
            for (int tp = 0; tp < 4; tp++) {
                int r = wn * 64 + tp * 16 + rBoff;
                uint32_t off = (uint32_t)r * 128 + (uint32_t)((((c0 + hiB) ^ (r & 7))) * 16);
                LDSM4(bH[2*tp][0], bH[2*tp][1], bH[2*tp+1][0], bH[2*tp+1][1], Bh + off);
            }
            #pragma unroll
            for (int tm = 0; tm < 2; tm++)
                #pragma unroll
                for (int tn = 0; tn < 8; tn++)
                    MMA16816(acc[tm][tn], aH[tm], bH[tn][0], bH[tn][1]);
        }
        __syncthreads();
    }

    // epilogue: unscale (B was x256), add bias, store
    const float inv256 = 1.0f / 256.0f;
    const int gid = lane >> 2, tig = lane & 3;
    #pragma unroll
    for (int tm = 0; tm < 2; tm++) {
        const int r0 = bm + wm * 32 + tm * 16 + gid;
        #pragma unroll
        for (int tn = 0; tn < 8; tn++) {
            const int col = bn + wn * 64 + tn * 8 + tig * 2;
            const float b0 = __ldg(&bias[col]);
            const float b1 = __ldg(&bias[col + 1]);
            float2 v0, v1;
            v0.x = acc[tm][tn][0] * inv256 + b0;
            v0.y = acc[tm][tn][1] * inv256 + b1;
            v1.x = acc[tm][tn][2] * inv256 + b0;
            v1.y = acc[tm][tn][3] * inv256 + b1;
            *reinterpret_cast<float2*>(&g_pre[(size_t)r0 * D_HID + col]) = v0;
            *reinterpret_cast<float2*>(&g_pre[(size_t)(r0 + 8) * D_HID + col]) = v1;
        }
    }
}

// ---------------- approx top-k radix select + margin candidate collection -----
__global__ __launch_bounds__(256) void topk_kernel() {
    extern __shared__ uint32_t u[];  // D_HID keys
    __shared__ int hist[256];
    __shared__ uint32_t s_prefix;
    __shared__ int s_remaining;
    __shared__ float s_thrm;
    __shared__ int s_cnt;

    const int row = blockIdx.x;
    const int t = threadIdx.x;
    const float* p = g_pre + (size_t)row * D_HID;

    for (int i = t; i < D_HID; i += 256) {
        uint32_t b = __float_as_uint(p[i]);
        u[i] = (b & 0x80000000u) ? ~b : (b | 0x80000000u);
    }
    if (t == 0) { s_prefix = 0; s_remaining = TOPK; s_cnt = 0; }
    __syncthreads();

    for (int byte = 3; byte >= 0; byte--) {
        hist[t] = 0;
        __syncthreads();
        const uint32_t prefix = s_prefix;
        const int shift = byte * 8;
        const uint32_t himask = (byte == 3) ? 0u : (0xFFFFFFFFu << (shift + 8));
        for (int i = t; i < D_HID; i += 256) {
            uint32_t v = u[i];
            if ((v & himask) == (prefix & himask))
                atomicAdd(&hist[(v >> shift) & 255], 1);
        }
        __syncthreads();
        if (t == 0) {
            int rem = s_remaining;
            int b = 255;
            for (; b > 0; b--) { if (hist[b] >= rem) break; rem -= hist[b]; }
            s_prefix = prefix | ((uint32_t)b << shift);
            s_remaining = rem;
        }
        __syncthreads();
    }

    // threshold (128th approx value) minus margin; collect candidates
    if (t == 0) {
        uint32_t key = s_prefix;
        uint32_t b = (key & 0x80000000u) ? (key & 0x7FFFFFFFu) : ~key;
        s_thrm = __uint_as_float(b) - MARGIN;
    }
    __syncthreads();
    const float thrm = s_thrm;
    for (int i = t; i < D_HID; i += 256) {
        uint32_t kk = u[i];
        uint32_t bb = (kk & 0x80000000u) ? (kk & 0x7FFFFFFFu) : ~kk;
        if (__uint_as_float(bb) >= thrm) {
            int pos = atomicAdd(&s_cnt, 1);
            if (pos < CAND_MAX) g_ci[(size_t)row * CAND_MAX + pos] = i;
        }
    }
    __syncthreads();
    if (t == 0) g_cn[row] = (s_cnt < CAND_MAX) ? s_cnt : CAND_MAX;
}

// ---------------- rescue: exact fp32 dots (R1-identical order) + top-128 ------
// One THREAD per candidate: single sequential fp32 FMA accumulator over
// k = 0..1023 (identical rounding order to the round-1 SIMT GEMM that passed
// at rel_err 7.85e-4), then + b_enc at the end.
__global__ __launch_bounds__(256) void rescue_kernel(const float* __restrict__ b_enc) {
    __shared__ float sx[D_MODEL];
    __shared__ float sv[CAND_MAX];
    __shared__ int   si[CAND_MAX];
    const int row = blockIdx.x;
    const int t = threadIdx.x;

    #pragma unroll
    for (int q = 0; q < 4; q++)
        sx[t + q * 256] = g_xn[(size_t)row * D_MODEL + t + q * 256];
    __syncthreads();
    const int C = g_cn[row];

    {
        if (t < C) {
            const int idx = g_ci[(size_t)row * CAND_MAX + t];
            const float* wt = g_bt + (size_t)idx * D_MODEL;
            float acc = 0.f;
            #pragma unroll 8
            for (int k = 0; k < D_MODEL; k++)
                acc = fmaf(sx[k], __ldg(&wt[k]), acc);   // strict sequential chain
            sv[t] = acc + __ldg(&b_enc[idx]);
            si[t] = idx;
        } else {
            sv[t] = -__int_as_float(0x7F800000);   // -inf
            si[t] = 0x7FFFFFFF;
        }
    }
    __syncthreads();

    // bitonic sort 256: val desc, idx asc (jax tie order)
    #pragma unroll 1
    for (int k = 2; k <= CAND_MAX; k <<= 1) {
        #pragma unroll 1
        for (int j = k >> 1; j > 0; j >>= 1) {
            const int ixj = t ^ j;
            if (ixj > t) {
                float v0 = sv[t], v1 = sv[ixj];
                int i0 = si[t], i1 = si[ixj];
                bool firstWins = (v0 > v1) || (v0 == v1 && i0 < i1);
                if (((t & k) == 0) != firstWins) {
                    sv[t] = v1; sv[ixj] = v0;
                    si[t] = i1; si[ixj] = i0;
                }
            }
            __syncthreads();
        }
    }

    if (t < TOPK) {
        g_tv[(size_t)row * TOPK + t] = fmaxf(sv[t], 0.0f);
        g_ti[(size_t)row * TOPK + t] = si[t];
    }
}

// ---------------- sparse decode + de-normalize -------------------------------
__global__ __launch_bounds__(256) void decode_kernel(const float* __restrict__ w_dec,
                                                     const float* __restrict__ b_pre,
                                                     float* __restrict__ out) {
    __shared__ float sval[TOPK];
    __shared__ int   sidx[TOPK];
    const int row = blockIdx.x;
    const int t = threadIdx.x;
    if (t < TOPK) {
        sval[t] = g_tv[(size_t)row * TOPK + t];
        sidx[t] = g_ti[(size_t)row * TOPK + t];
    }
    __syncthreads();

    float acc0 = 0.f, acc1 = 0.f, acc2 = 0.f, acc3 = 0.f;
    #pragma unroll 4
    for (int j = 0; j < TOPK; j++) {
        const float v = sval[j];
        const float* wr = w_dec + (size_t)sidx[j] * D_MODEL;
        acc0 += v * __ldg(&wr[t]);
        acc1 += v * __ldg(&wr[t + 256]);
        acc2 += v * __ldg(&wr[t + 512]);
        acc3 += v * __ldg(&wr[t + 768]);
    }
    const float m = g_mu[row], s = g_sd[row];
    float* o = out + (size_t)row * D_MODEL;
    o[t]       = (acc0 + b_pre[t])       * s + m;
    o[t + 256] = (acc1 + b_pre[t + 256]) * s + m;
    o[t + 512] = (acc2 + b_pre[t + 512]) * s + m;
    o[t + 768] = (acc3 + b_pre[t + 768]) * s + m;
}

// ---------------- launch ------------------------------------------------------
extern "C" void kernel_launch(void* const* d_in, const int* in_sizes, int n_in,
                              void* d_out, int out_size) {
    const float* x     = (const float*)d_in[0];
    const float* w_enc = (const float*)d_in[1];
    const float* w_dec = (const float*)d_in[2];
    const float* b_enc = (const float*)d_in[3];
    const float* b_pre = (const float*)d_in[4];
    float* out = (float*)d_out;

    // 1. LayerNorm (fp32 out + fp16 copy)
    ln_kernel<<<N_TOK, 256>>>(x, b_pre);

    // 2. Transpose w_enc -> fp32 + fp16(x256) [D_HID, D_MODEL]
    dim3 tg(D_HID / 32, D_MODEL / 32);
    transpose_split<<<tg, dim3(32, 8)>>>(w_enc);

    // 3. Approximate HMMA encoder GEMM (single fp16 product)
    cudaFuncSetAttribute(enc_gemm_mma, cudaFuncAttributeMaxDynamicSharedMemorySize, GEMM_SMEM);
    dim3 ggrid(N_TOK / TM, D_HID / TN);
    enc_gemm_mma<<<ggrid, 256, GEMM_SMEM>>>(b_enc);

    // 4. Approx radix top-128 + margin candidate collection
    cudaFuncSetAttribute(topk_kernel, cudaFuncAttributeMaxDynamicSharedMemorySize,
                         D_HID * (int)sizeof(uint32_t));
    topk_kernel<<<N_TOK, 256, D_HID * sizeof(uint32_t)>>>();

    // 5. Rescue: R1-identical sequential fp32 dots for candidates, exact top-128
    rescue_kernel<<<N_TOK, 256>>>(b_enc);

    // 6. Sparse decode + un-normalize
    decode_kernel<<<N_TOK, 256>>>(w_dec, b_pre, out);
}

// round 6
// speedup vs baseline: 3.5780x; 1.3996x over previous
#include <cuda_runtime.h>
#include <cuda_fp16.h>
#include <cstdint>

// Problem constants
#define N_TOK   4096
#define D_MODEL 1024
#define D_HID   32768
#define TOPK    128
#define EPS     1e-5f
#define CAND_MAX 256
#define MARGIN  4e-3f

// GEMM tiling
#define TM   128
#define TN   128
#define TKC  64                          // k-halfs per chunk (128B rows)
#define NCHUNK (D_MODEL / TKC)           // 16
#define STAGE_BYTES 32768                // ah(16K) + bh(16K)
#define GEMM_SMEM (2 * STAGE_BYTES)      // 64 KB

// Rescue tiling
#define RTILE 64
#define RPAD  65
// dyn smem: sx[1024] | sw[CAND_MAX][RPAD] | sv[256] | si[256]
#define RES_SMEM ((D_MODEL + CAND_MAX * RPAD + CAND_MAX + CAND_MAX) * 4)

// ---------------- scratch (device globals; no allocs allowed) ----------------
__device__ __half g_ah[(size_t)N_TOK * D_MODEL];           // xn fp16
__device__ float  g_xn[(size_t)N_TOK * D_MODEL];           // xn fp32 (rescue)
__device__ __half g_bh[(size_t)D_HID * D_MODEL];           // (256*w_enc)^T fp16
__device__ float  g_bt[(size_t)D_HID * D_MODEL];           // w_enc^T fp32 (rescue)
__device__ float g_pre[(size_t)N_TOK * D_HID];             // 512 MB approx pre-acts
__device__ float g_mu[N_TOK];
__device__ float g_sd[N_TOK];
__device__ int   g_ci[(size_t)N_TOK * CAND_MAX];           // candidate indices
__device__ int   g_cn[N_TOK];                              // candidate counts
__device__ float g_tv[(size_t)N_TOK * TOPK];
__device__ int   g_ti[(size_t)N_TOK * TOPK];

// ---------------- PTX helpers -------------------------------------------------
__device__ __forceinline__ uint32_t smem_u32(const void* p) {
    uint32_t a;
    asm("{ .reg .u64 t; cvta.to.shared.u64 t, %1; cvt.u32.u64 %0, t; }" : "=r"(a) : "l"(p));
    return a;
}
__device__ __forceinline__ void cp16(uint32_t dst, const void* src) {
    asm volatile("cp.async.cg.shared.global [%0], [%1], 16;" :: "r"(dst), "l"(src) : "memory");
}
#define CP_COMMIT()   asm volatile("cp.async.commit_group;" ::: "memory")
#define CP_WAIT(n)    asm volatile("cp.async.wait_group %0;" :: "n"(n) : "memory")

#define LDSM4(R0, R1, R2, R3, A)                                                  \
    asm volatile("ldmatrix.sync.aligned.m8n8.x4.shared.b16 {%0,%1,%2,%3}, [%4];"  \
        : "=r"(R0), "=r"(R1), "=r"(R2), "=r"(R3) : "r"(A))

#define MMA16816(D, A, B0, B1)                                                    \
    asm volatile("mma.sync.aligned.m16n8k16.row.col.f32.f16.f16.f32 "             \
        "{%0,%1,%2,%3}, {%4,%5,%6,%7}, {%8,%9}, {%0,%1,%2,%3};"                   \
        : "+f"((D)[0]), "+f"((D)[1]), "+f"((D)[2]), "+f"((D)[3])                   \
        : "r"((A)[0]), "r"((A)[1]), "r"((A)[2]), "r"((A)[3]), "r"(B0), "r"(B1))

// ---------------- LayerNorm ----------------------------------------------------
__device__ __forceinline__ float block_reduce_sum256(float v, float* red) {
    #pragma unroll
    for (int o = 16; o > 0; o >>= 1) v += __shfl_xor_sync(0xffffffffu, v, o);
    int w = threadIdx.x >> 5;
    if ((threadIdx.x & 31) == 0) red[w] = v;
    __syncthreads();
    float r = (threadIdx.x < 8) ? red[threadIdx.x] : 0.f;
    if (threadIdx.x < 32) {
        #pragma unroll
        for (int o = 4; o > 0; o >>= 1) r += __shfl_xor_sync(0xffffffffu, r, o);
        if (threadIdx.x == 0) red[0] = r;
    }
    __syncthreads();
    float out = red[0];
    __syncthreads();
    return out;
}

__global__ __launch_bounds__(256) void ln_kernel(const float* __restrict__ x,
                                                 const float* __restrict__ b_pre) {
    __shared__ float sx[D_MODEL];
    __shared__ float red[32];
    const int row = blockIdx.x;
    const int t = threadIdx.x;
    const float* xr = x + (size_t)row * D_MODEL;

    float sum = 0.f;
    #pragma unroll
    for (int q = 0; q < 4; q++) { float f = xr[t + q * 256]; sx[t + q * 256] = f; sum += f; }
    float m = block_reduce_sum256(sum, red) * (1.0f / D_MODEL);

    float sq = 0.f;
    #pragma unroll
    for (int q = 0; q < 4; q++) { float c = sx[t + q * 256] - m; sq += c * c; }
    float sd = sqrtf(block_reduce_sum256(sq, red) * (1.0f / (D_MODEL - 1)));
    float inv = 1.0f / (sd + EPS);

    #pragma unroll
    for (int q = 0; q < 4; q++) {
        int col = t + q * 256;
        float v = (sx[col] - m) * inv - b_pre[col];
        size_t idx = (size_t)row * D_MODEL + col;
        g_xn[idx] = v;
        g_ah[idx] = __float2half_rn(v);
    }
    if (t == 0) { g_mu[row] = m; g_sd[row] = sd; }
}

// ---------------- transpose: w_enc -> [D_HID, D_MODEL] fp32 + fp16(x256) ------
__global__ __launch_bounds__(256) void transpose_split(const float* __restrict__ w) {
    __shared__ float tile[32][33];
    const int n0 = blockIdx.x * 32, k0 = blockIdx.y * 32;
    const int tx = threadIdx.x, ty = threadIdx.y;
    #pragma unroll
    for (int i = 0; i < 32; i += 8)
        tile[ty + i][tx] = w[(size_t)(k0 + ty + i) * D_HID + n0 + tx];
    __syncthreads();
    #pragma unroll
    for (int i = 0; i < 32; i += 8) {
        float v = tile[tx][ty + i];
        size_t idx = (size_t)(n0 + ty + i) * D_MODEL + k0 + tx;
        g_bt[idx] = v;
        g_bh[idx] = __float2half_rn(v * 256.0f);   // scale so small entries stay normal
    }
}

// ---------------- HMMA GEMM (approx, single fp16 product) ---------------------
// A tiles [128 x 64] halfs (row=m, 128B/row), B tiles [128 x 64] (row=n),
// XOR swizzle: 16B chunk c at row r stored at c ^ (r & 7).
__device__ __forceinline__ void load_chunk(uint32_t stage, int bm, int bn, int k0, int t) {
    #pragma unroll
    for (int i = 0; i < 4; i++) {
        int g = t + i * 256;                // 0..1023
        int row = g >> 3, ch = g & 7;
        uint32_t dst = stage + (uint32_t)row * 128 + (uint32_t)((ch ^ (row & 7)) * 16);
        cp16(dst,         g_ah + (size_t)(bm + row) * D_MODEL + k0 + ch * 8);
        cp16(dst + 16384, g_bh + (size_t)(bn + row) * D_MODEL + k0 + ch * 8);
    }
}

__global__ __launch_bounds__(256, 1) void enc_gemm_mma(const float* __restrict__ bias) {
    extern __shared__ __align__(1024) char smem[];
    const uint32_t sb = smem_u32(smem);
    const int t = threadIdx.x;
    const int wid = t >> 5, lane = t & 31;
    const int wm = wid >> 1, wn = wid & 1;      // 4x2 warps, warp tile 32x64
    const int bm = blockIdx.x * TM;
    const int bn = blockIdx.y * TN;

    float acc[2][8][4];
    #pragma unroll
    for (int i = 0; i < 2; i++)
        #pragma unroll
        for (int j = 0; j < 8; j++)
            #pragma unroll
            for (int q = 0; q < 4; q++) acc[i][j][q] = 0.f;

    const int laneA = lane & 15;
    const int hiA   = lane >> 4;
    const int rBoff = (lane & 7) + ((lane >> 4) << 3);
    const int hiB   = (lane >> 3) & 1;

    load_chunk(sb, bm, bn, 0, t);
    CP_COMMIT();

    for (int c = 0; c < NCHUNK; c++) {
        if (c + 1 < NCHUNK) {
            load_chunk(sb + (uint32_t)((c + 1) & 1) * STAGE_BYTES, bm, bn, (c + 1) * TKC, t);
            CP_COMMIT();
            CP_WAIT(1);
        } else {
            CP_WAIT(0);
        }
        __syncthreads();

        const uint32_t base = sb + (uint32_t)(c & 1) * STAGE_BYTES;
        const uint32_t Ah = base, Bh = base + 16384;

        #pragma unroll
        for (int ks = 0; ks < 4; ks++) {
            const int c0 = ks * 2;
            uint32_t aH[2][4], bH[8][2];
            #pragma unroll
            for (int tm = 0; tm < 2; tm++) {
                int r = wm * 32 + tm * 16 + laneA;
                uint32_t off = (uint32_t)r * 128 + (uint32_t)((((c0 + hiA) ^ (r & 7))) * 16);
                LDSM4(aH[tm][0], aH[tm][1], aH[tm][2], aH[tm][3], Ah + off);
            }
            #pragma unroll
            for (int tp = 0; tp < 4; tp++) {
                int r = wn * 64 + tp * 16 + rBoff;
                uint32_t off = (uint32_t)r * 128 + (uint32_t)((((c0 + hiB) ^ (r & 7))) * 16);
                LDSM4(bH[2*tp][0], bH[2*tp][1], bH[2*tp+1][0], bH[2*tp+1][1], Bh + off);
            }
            #pragma unroll
            for (int tm = 0; tm < 2; tm++)
                #pragma unroll
                for (int tn = 0; tn < 8; tn++)
                    MMA16816(acc[tm][tn], aH[tm], bH[tn][0], bH[tn][1]);
        }
        __syncthreads();
    }

    // epilogue: unscale (B was x256), add bias, store
    const float inv256 = 1.0f / 256.0f;
    const int gid = lane >> 2, tig = lane & 3;
    #pragma unroll
    for (int tm = 0; tm < 2; tm++) {
        const int r0 = bm + wm * 32 + tm * 16 + gid;
        #pragma unroll
        for (int tn = 0; tn < 8; tn++) {
            const int col = bn + wn * 64 + tn * 8 + tig * 2;
            const float b0 = __ldg(&bias[col]);
            const float b1 = __ldg(&bias[col + 1]);
            float2 v0, v1;
            v0.x = acc[tm][tn][0] * inv256 + b0;
            v0.y = acc[tm][tn][1] * inv256 + b1;
            v1.x = acc[tm][tn][2] * inv256 + b0;
            v1.y = acc[tm][tn][3] * inv256 + b1;
            *reinterpret_cast<float2*>(&g_pre[(size_t)r0 * D_HID + col]) = v0;
            *reinterpret_cast<float2*>(&g_pre[(size_t)(r0 + 8) * D_HID + col]) = v1;
        }
    }
}

// ---------------- approx top-k radix select + margin candidate collection -----
__global__ __launch_bounds__(256) void topk_kernel() {
    extern __shared__ uint32_t u[];  // D_HID keys
    __shared__ int hist[256];
    __shared__ uint32_t s_prefix;
    __shared__ int s_remaining;
    __shared__ float s_thrm;
    __shared__ int s_cnt;

    const int row = blockIdx.x;
    const int t = threadIdx.x;
    const float* p = g_pre + (size_t)row * D_HID;

    for (int i = t; i < D_HID; i += 256) {
        uint32_t b = __float_as_uint(p[i]);
        u[i] = (b & 0x80000000u) ? ~b : (b | 0x80000000u);
    }
    if (t == 0) { s_prefix = 0; s_remaining = TOPK; s_cnt = 0; }
    __syncthreads();

    for (int byte = 3; byte >= 0; byte--) {
        hist[t] = 0;
        __syncthreads();
        const uint32_t prefix = s_prefix;
        const int shift = byte * 8;
        const uint32_t himask = (byte == 3) ? 0u : (0xFFFFFFFFu << (shift + 8));
        for (int i = t; i < D_HID; i += 256) {
            uint32_t v = u[i];
            if ((v & himask) == (prefix & himask))
                atomicAdd(&hist[(v >> shift) & 255], 1);
        }
        __syncthreads();
        if (t == 0) {
            int rem = s_remaining;
            int b = 255;
            for (; b > 0; b--) { if (hist[b] >= rem) break; rem -= hist[b]; }
            s_prefix = prefix | ((uint32_t)b << shift);
            s_remaining = rem;
        }
        __syncthreads();
    }

    // threshold (128th approx value) minus margin; collect candidates
    if (t == 0) {
        uint32_t key = s_prefix;
        uint32_t b = (key & 0x80000000u) ? (key & 0x7FFFFFFFu) : ~key;
        s_thrm = __uint_as_float(b) - MARGIN;
    }
    __syncthreads();
    const float thrm = s_thrm;
    for (int i = t; i < D_HID; i += 256) {
        uint32_t kk = u[i];
        uint32_t bb = (kk & 0x80000000u) ? (kk & 0x7FFFFFFFu) : ~kk;
        if (__uint_as_float(bb) >= thrm) {
            int pos = atomicAdd(&s_cnt, 1);
            if (pos < CAND_MAX) g_ci[(size_t)row * CAND_MAX + pos] = i;
        }
    }
    __syncthreads();
    if (t == 0) g_cn[row] = (s_cnt < CAND_MAX) ? s_cnt : CAND_MAX;
}

// ---------------- rescue: exact fp32 dots (R1-identical order) + top-128 ------
// One THREAD per candidate, but w rows staged through smem in coalesced
// 64-wide tiles. The per-candidate FMA chain (k = 0..1023, single fp32
// accumulator) is IDENTICAL in order/rounding to R1's passing GEMM.
__global__ __launch_bounds__(256, 2) void rescue_kernel(const float* __restrict__ b_enc) {
    extern __shared__ float dyn[];
    float* sx = dyn;                                   // [D_MODEL]
    float* sw = dyn + D_MODEL;                         // [CAND_MAX][RPAD]
    float* sv = sw + CAND_MAX * RPAD;                  // [CAND_MAX]
    int*   si = (int*)(sv + CAND_MAX);                 // [CAND_MAX]

    const int row = blockIdx.x;
    const int t = threadIdx.x;

    #pragma unroll
    for (int q = 0; q < 4; q++)
        sx[t + q * 256] = g_xn[(size_t)row * D_MODEL + t + q * 256];
    si[t] = (t < g_cn[row]) ? g_ci[(size_t)row * CAND_MAX + t] : 0x7FFFFFFF;
    __syncthreads();
    const int C = g_cn[row];
    const int myIdx = si[t];

    float acc = 0.f;
    for (int k0 = 0; k0 < D_MODEL; k0 += RTILE) {
        // coalesced stage: 16 threads x float4 per candidate row segment
        const int q = t & 15;                // 16 float4 = 64 floats
        #pragma unroll
        for (int pass = 0; pass < 16; pass++) {
            const int c = pass * 16 + (t >> 4);
            if (c < C) {
                const float4 v = *reinterpret_cast<const float4*>(
                    g_bt + (size_t)si[c] * D_MODEL + k0 + q * 4);
                float* dst = sw + c * RPAD + q * 4;
                dst[0] = v.x; dst[1] = v.y; dst[2] = v.z; dst[3] = v.w;
            }
        }
        __syncthreads();
        if (t < C) {
            const float* wrow = sw + t * RPAD;
            #pragma unroll
            for (int kk = 0; kk < RTILE; kk++)
                acc = fmaf(sx[k0 + kk], wrow[kk], acc);   // strict sequential chain
        }
        __syncthreads();
    }

    if (t < C) {
        sv[t] = acc + __ldg(&b_enc[myIdx]);
    } else {
        sv[t] = -__int_as_float(0x7F800000);   // -inf
    }
    __syncthreads();

    // bitonic sort 256: val desc, idx asc (jax tie order)
    #pragma unroll 1
    for (int k = 2; k <= CAND_MAX; k <<= 1) {
        #pragma unroll 1
        for (int j = k >> 1; j > 0; j >>= 1) {
            const int ixj = t ^ j;
            if (ixj > t) {
                float v0 = sv[t], v1 = sv[ixj];
                int i0 = si[t], i1 = si[ixj];
                bool firstWins = (v0 > v1) || (v0 == v1 && i0 < i1);
                if (((t & k) == 0) != firstWins) {
                    sv[t] = v1; sv[ixj] = v0;
                    si[t] = i1; si[ixj] = i0;
                }
            }
            __syncthreads();
        }
    }

    if (t < TOPK) {
        g_tv[(size_t)row * TOPK + t] = fmaxf(sv[t], 0.0f);
        g_ti[(size_t)row * TOPK + t] = si[t];
    }
}

// ---------------- sparse decode + de-normalize -------------------------------
__global__ __launch_bounds__(256) void decode_kernel(const float* __restrict__ w_dec,
                                                     const float* __restrict__ b_pre,
                                                     float* __restrict__ out) {
    __shared__ float sval[TOPK];
    __shared__ int   sidx[TOPK];
    const int row = blockIdx.x;
    const int t = threadIdx.x;
    if (t < TOPK) {
        sval[t] = g_tv[(size_t)row * TOPK + t];
        sidx[t] = g_ti[(size_t)row * TOPK + t];
    }
    __syncthreads();

    float acc0 = 0.f, acc1 = 0.f, acc2 = 0.f, acc3 = 0.f;
    #pragma unroll 4
    for (int j = 0; j < TOPK; j++) {
        const float v = sval[j];
        const float* wr = w_dec + (size_t)sidx[j] * D_MODEL;
        acc0 += v * __ldg(&wr[t]);
        acc1 += v * __ldg(&wr[t + 256]);
        acc2 += v * __ldg(&wr[t + 512]);
        acc3 += v * __ldg(&wr[t + 768]);
    }
    const float m = g_mu[row], s = g_sd[row];
    float* o = out + (size_t)row * D_MODEL;
    o[t]       = (acc0 + b_pre[t])       * s + m;
    o[t + 256] = (acc1 + b_pre[t + 256]) * s + m;
    o[t + 512] = (acc2 + b_pre[t + 512]) * s + m;
    o[t + 768] = (acc3 + b_pre[t + 768]) * s + m;
}

// ---------------- launch ------------------------------------------------------
extern "C" void kernel_launch(void* const* d_in, const int* in_sizes, int n_in,
                              void* d_out, int out_size) {
    const float* x     = (const float*)d_in[0];
    const float* w_enc = (const float*)d_in[1];
    const float* w_dec = (const float*)d_in[2];
    const float* b_enc = (const float*)d_in[3];
    const float* b_pre = (const float*)d_in[4];
    float* out = (float*)d_out;

    // 1. LayerNorm (fp32 out + fp16 copy)
    ln_kernel<<<N_TOK, 256>>>(x, b_pre);

    // 2. Transpose w_enc -> fp32 + fp16(x256) [D_HID, D_MODEL]
    dim3 tg(D_HID / 32, D_MODEL / 32);
    transpose_split<<<tg, dim3(32, 8)>>>(w_enc);

    // 3. Approximate HMMA encoder GEMM (single fp16 product)
    cudaFuncSetAttribute(enc_gemm_mma, cudaFuncAttributeMaxDynamicSharedMemorySize, GEMM_SMEM);
    dim3 ggrid(N_TOK / TM, D_HID / TN);
    enc_gemm_mma<<<ggrid, 256, GEMM_SMEM>>>(b_enc);

    // 4. Approx radix top-128 + margin candidate collection
    cudaFuncSetAttribute(topk_kernel, cudaFuncAttributeMaxDynamicSharedMemorySize,
                         D_HID * (int)sizeof(uint32_t));
    topk_kernel<<<N_TOK, 256, D_HID * sizeof(uint32_t)>>>();

    // 5. Rescue: R1-identical sequential fp32 dots, smem-staged coalesced loads
    cudaFuncSetAttribute(rescue_kernel, cudaFuncAttributeMaxDynamicSharedMemorySize, RES_SMEM);
    rescue_kernel<<<N_TOK, 256, RES_SMEM>>>(b_enc);

    // 6. Sparse decode + un-normalize
    decode_kernel<<<N_TOK, 256>>>(w_dec, b_pre, out);
}

// round 7
// speedup vs baseline: 6.3498x; 1.7747x over previous
#include <cuda_runtime.h>
#include <cuda_fp16.h>
#include <cstdint>

// Problem constants
#define N_TOK   4096
#define D_MODEL 1024
#define D_HID   32768
#define TOPK    128
#define EPS     1e-5f
#define CAND_MAX 256
#define MARGIN  4e-3f
#define NBINS   4096

// GEMM tiling
#define TM   128
#define TN   128
#define TKC  64                          // k-halfs per chunk (128B rows)
#define NCHUNK (D_MODEL / TKC)           // 16
#define STAGE_BYTES 32768                // ah(16K) + bh(16K)
#define GEMM_SMEM (2 * STAGE_BYTES)      // 64 KB

// Rescue tiling
#define RTILE 64
#define RPAD  65
#define RES_SMEM ((D_MODEL + CAND_MAX * RPAD + CAND_MAX + CAND_MAX) * 4)

// ---------------- scratch (device globals; no allocs allowed) ----------------
__device__ __half g_ah[(size_t)N_TOK * D_MODEL];           // xn fp16
__device__ float  g_xn[(size_t)N_TOK * D_MODEL];           // xn fp32 (rescue)
__device__ __half g_bh[(size_t)D_HID * D_MODEL];           // (256*w_enc)^T fp16
__device__ float  g_bt[(size_t)D_HID * D_MODEL];           // w_enc^T fp32 (rescue)
__device__ __half g_preh[(size_t)N_TOK * D_HID];           // 256 MB approx pre-acts
__device__ float g_mu[N_TOK];
__device__ float g_sd[N_TOK];
__device__ int   g_ci[(size_t)N_TOK * CAND_MAX];           // candidate indices
__device__ int   g_cn[N_TOK];                              // candidate counts
__device__ float g_tv[(size_t)N_TOK * TOPK];
__device__ int   g_ti[(size_t)N_TOK * TOPK];

// ---------------- PTX helpers -------------------------------------------------
__device__ __forceinline__ uint32_t smem_u32(const void* p) {
    uint32_t a;
    asm("{ .reg .u64 t; cvta.to.shared.u64 t, %1; cvt.u32.u64 %0, t; }" : "=r"(a) : "l"(p));
    return a;
}
__device__ __forceinline__ void cp16(uint32_t dst, const void* src) {
    asm volatile("cp.async.cg.shared.global [%0], [%1], 16;" :: "r"(dst), "l"(src) : "memory");
}
#define CP_COMMIT()   asm volatile("cp.async.commit_group;" ::: "memory")
#define CP_WAIT(n)    asm volatile("cp.async.wait_group %0;" :: "n"(n) : "memory")

#define LDSM4(R0, R1, R2, R3, A)                                                  \
    asm volatile("ldmatrix.sync.aligned.m8n8.x4.shared.b16 {%0,%1,%2,%3}, [%4];"  \
        : "=r"(R0), "=r"(R1), "=r"(R2), "=r"(R3) : "r"(A))

#define MMA16816(D, A, B0, B1)                                                    \
    asm volatile("mma.sync.aligned.m16n8k16.row.col.f32.f16.f16.f32 "             \
        "{%0,%1,%2,%3}, {%4,%5,%6,%7}, {%8,%9}, {%0,%1,%2,%3};"                   \
        : "+f"((D)[0]), "+f"((D)[1]), "+f"((D)[2]), "+f"((D)[3])                   \
        : "r"((A)[0]), "r"((A)[1]), "r"((A)[2]), "r"((A)[3]), "r"(B0), "r"(B1))

// ---------------- LayerNorm ----------------------------------------------------
__device__ __forceinline__ float block_reduce_sum256(float v, float* red) {
    #pragma unroll
    for (int o = 16; o > 0; o >>= 1) v += __shfl_xor_sync(0xffffffffu, v, o);
    int w = threadIdx.x >> 5;
    if ((threadIdx.x & 31) == 0) red[w] = v;
    __syncthreads();
    float r = (threadIdx.x < 8) ? red[threadIdx.x] : 0.f;
    if (threadIdx.x < 32) {
        #pragma unroll
        for (int o = 4; o > 0; o >>= 1) r += __shfl_xor_sync(0xffffffffu, r, o);
        if (threadIdx.x == 0) red[0] = r;
    }
    __syncthreads();
    float out = red[0];
    __syncthreads();
    return out;
}

__global__ __launch_bounds__(256) void ln_kernel(const float* __restrict__ x,
                                                 const float* __restrict__ b_pre) {
    __shared__ float sx[D_MODEL];
    __shared__ float red[32];
    const int row = blockIdx.x;
    const int t = threadIdx.x;
    const float* xr = x + (size_t)row * D_MODEL;

    float sum = 0.f;
    #pragma unroll
    for (int q = 0; q < 4; q++) { float f = xr[t + q * 256]; sx[t + q * 256] = f; sum += f; }
    float m = block_reduce_sum256(sum, red) * (1.0f / D_MODEL);

    float sq = 0.f;
    #pragma unroll
    for (int q = 0; q < 4; q++) { float c = sx[t + q * 256] - m; sq += c * c; }
    float sd = sqrtf(block_reduce_sum256(sq, red) * (1.0f / (D_MODEL - 1)));
    float inv = 1.0f / (sd + EPS);

    #pragma unroll
    for (int q = 0; q < 4; q++) {
        int col = t + q * 256;
        float v = (sx[col] - m) * inv - b_pre[col];
        size_t idx = (size_t)row * D_MODEL + col;
        g_xn[idx] = v;
        g_ah[idx] = __float2half_rn(v);
    }
    if (t == 0) { g_mu[row] = m; g_sd[row] = sd; }
}

// ---------------- transpose: w_enc -> [D_HID, D_MODEL] fp32 + fp16(x256) ------
__global__ __launch_bounds__(256) void transpose_split(const float* __restrict__ w) {
    __shared__ float tile[32][33];
    const int n0 = blockIdx.x * 32, k0 = blockIdx.y * 32;
    const int tx = threadIdx.x, ty = threadIdx.y;
    #pragma unroll
    for (int i = 0; i < 32; i += 8)
        tile[ty + i][tx] = w[(size_t)(k0 + ty + i) * D_HID + n0 + tx];
    __syncthreads();
    #pragma unroll
    for (int i = 0; i < 32; i += 8) {
        float v = tile[tx][ty + i];
        size_t idx = (size_t)(n0 + ty + i) * D_MODEL + k0 + tx;
        g_bt[idx] = v;
        g_bh[idx] = __float2half_rn(v * 256.0f);   // scale so small entries stay normal
    }
}

// ---------------- HMMA GEMM (approx, single fp16 product) ---------------------
__device__ __forceinline__ void load_chunk(uint32_t stage, int bm, int bn, int k0, int t) {
    #pragma unroll
    for (int i = 0; i < 4; i++) {
        int g = t + i * 256;                // 0..1023
        int row = g >> 3, ch = g & 7;
        uint32_t dst = stage + (uint32_t)row * 128 + (uint32_t)((ch ^ (row & 7)) * 16);
        cp16(dst,         g_ah + (size_t)(bm + row) * D_MODEL + k0 + ch * 8);
        cp16(dst + 16384, g_bh + (size_t)(bn + row) * D_MODEL + k0 + ch * 8);
    }
}

__global__ __launch_bounds__(256, 2) void enc_gemm_mma(const float* __restrict__ bias) {
    extern __shared__ __align__(1024) char smem[];
    const uint32_t sb = smem_u32(smem);
    const int t = threadIdx.x;
    const int wid = t >> 5, lane = t & 31;
    const int wm = wid >> 1, wn = wid & 1;      // 4x2 warps, warp tile 32x64
    const int bm = blockIdx.x * TM;
    const int bn = blockIdx.y * TN;

    float acc[2][8][4];
    #pragma unroll
    for (int i = 0; i < 2; i++)
        #pragma unroll
        for (int j = 0; j < 8; j++)
            #pragma unroll
            for (int q = 0; q < 4; q++) acc[i][j][q] = 0.f;

    const int laneA = lane & 15;
    const int hiA   = lane >> 4;
    const int rBoff = (lane & 7) + ((lane >> 4) << 3);
    const int hiB   = (lane >> 3) & 1;

    load_chunk(sb, bm, bn, 0, t);
    CP_COMMIT();

    for (int c = 0; c < NCHUNK; c++) {
        if (c + 1 < NCHUNK) {
            load_chunk(sb + (uint32_t)((c + 1) & 1) * STAGE_BYTES, bm, bn, (c + 1) * TKC, t);
            CP_COMMIT();
            CP_WAIT(1);
        } else {
            CP_WAIT(0);
        }
        __syncthreads();

        const uint32_t base = sb + (uint32_t)(c & 1) * STAGE_BYTES;
        const uint32_t Ah = base, Bh = base + 16384;

        #pragma unroll
        for (int ks = 0; ks < 4; ks++) {
            const int c0 = ks * 2;
            uint32_t aH[2][4], bH[8][2];
            #pragma unroll
            for (int tm = 0; tm < 2; tm++) {
                int r = wm * 32 + tm * 16 + laneA;
                uint32_t off = (uint32_t)r * 128 + (uint32_t)((((c0 + hiA) ^ (r & 7))) * 16);
                LDSM4(aH[tm][0], aH[tm][1], aH[tm][2], aH[tm][3], Ah + off);
            }
            #pragma unroll
            for (int tp = 0; tp < 4; tp++) {
                int r = wn * 64 + tp * 16 + rBoff;
                uint32_t off = (uint32_t)r * 128 + (uint32_t)((((c0 + hiB) ^ (r & 7))) * 16);
                LDSM4(bH[2*tp][0], bH[2*tp][1], bH[2*tp+1][0], bH[2*tp+1][1], Bh + off);
            }
            #pragma unroll
            for (int tm = 0; tm < 2; tm++)
                #pragma unroll
                for (int tn = 0; tn < 8; tn++)
                    MMA16816(acc[tm][tn], aH[tm], bH[tn][0], bH[tn][1]);
        }
        __syncthreads();
    }

    // epilogue: unscale (B was x256), add bias, store fp16
    const float inv256 = 1.0f / 256.0f;
    const int gid = lane >> 2, tig = lane & 3;
    #pragma unroll
    for (int tm = 0; tm < 2; tm++) {
        const int r0 = bm + wm * 32 + tm * 16 + gid;
        #pragma unroll
        for (int tn = 0; tn < 8; tn++) {
            const int col = bn + wn * 64 + tn * 8 + tig * 2;
            const float b0 = __ldg(&bias[col]);
            const float b1 = __ldg(&bias[col + 1]);
            __half2 h0 = __floats2half2_rn(acc[tm][tn][0] * inv256 + b0,
                                           acc[tm][tn][1] * inv256 + b1);
            __half2 h1 = __floats2half2_rn(acc[tm][tn][2] * inv256 + b0,
                                           acc[tm][tn][3] * inv256 + b1);
            *reinterpret_cast<__half2*>(&g_preh[(size_t)r0 * D_HID + col]) = h0;
            *reinterpret_cast<__half2*>(&g_preh[(size_t)(r0 + 8) * D_HID + col]) = h1;
        }
    }
}

// ---------------- topk: fp16-key histogram select + candidate collection ------
// Monotonic 16-bit key; 4096 bins = key>>4 (bin width ~2^-6 relative).
// Find bin where from-top suffix count crosses TOPK; thr = bin lower edge - margin.
__device__ __forceinline__ int bin_of_half_bits(uint32_t h) {
    uint32_t k = (h & 0x8000u) ? ((~h) & 0xFFFFu) : (h | 0x8000u);
    return (int)(k >> 4);
}

__global__ __launch_bounds__(256) void topk_kernel() {
    __shared__ int hist[NBINS];            // 16 KB
    __shared__ int segs[256];
    __shared__ int warpTot[8];
    __shared__ float s_thr;
    __shared__ int s_cnt;

    const int row = blockIdx.x;
    const int t = threadIdx.x;
    const int lane = t & 31, wid = t >> 5;
    const uint4* p4 = reinterpret_cast<const uint4*>(g_preh + (size_t)row * D_HID);

    #pragma unroll
    for (int i = 0; i < NBINS / 256; i++) hist[t + i * 256] = 0;
    if (t == 0) s_cnt = 0;
    __syncthreads();

    // pass 1: histogram (8 halfs per uint4)
    #pragma unroll
    for (int i = 0; i < D_HID / 8 / 256; i++) {
        uint4 v = p4[t + i * 256];
        uint32_t w0 = v.x, w1 = v.y, w2 = v.z, w3 = v.w;
        atomicAdd(&hist[bin_of_half_bits(w0 & 0xFFFFu)], 1);
        atomicAdd(&hist[bin_of_half_bits(w0 >> 16)], 1);
        atomicAdd(&hist[bin_of_half_bits(w1 & 0xFFFFu)], 1);
        atomicAdd(&hist[bin_of_half_bits(w1 >> 16)], 1);
        atomicAdd(&hist[bin_of_half_bits(w2 & 0xFFFFu)], 1);
        atomicAdd(&hist[bin_of_half_bits(w2 >> 16)], 1);
        atomicAdd(&hist[bin_of_half_bits(w3 & 0xFFFFu)], 1);
        atomicAdd(&hist[bin_of_half_bits(w3 >> 16)], 1);
    }
    __syncthreads();

    // suffix-count crossing: segment = 16 bins per thread
    int seg = 0;
    #pragma unroll
    for (int k = 0; k < 16; k++) seg += hist[t * 16 + k];
    segs[t] = seg;
    int wsum = seg;
    #pragma unroll
    for (int o = 16; o > 0; o >>= 1) wsum += __shfl_xor_sync(0xffffffffu, wsum, o);
    if (lane == 0) warpTot[wid] = wsum;
    __syncthreads();

    if (t == 0) {
        int cum = 0, w = 7;
        for (; w > 0; w--) { if (cum + warpTot[w] >= TOPK) break; cum += warpTot[w]; }
        int s = w * 32 + 31;
        for (; s > w * 32; s--) { if (cum + segs[s] >= TOPK) break; cum += segs[s]; }
        int b = s * 16 + 15;
        for (; b > s * 16; b--) { if (cum + hist[b] >= TOPK) break; cum += hist[b]; }
        // lower edge of bin b -> half bits -> value
        uint32_t keyLo = (uint32_t)b << 4;
        uint32_t hbits = (keyLo & 0x8000u) ? (keyLo & 0x7FFFu) : ((~keyLo) & 0xFFFFu);
        __half_raw hr; hr.x = (unsigned short)hbits;
        s_thr = __half2float(__half(hr)) - MARGIN;
    }
    __syncthreads();

    // pass 2: collect candidates >= thr
    const float thr = s_thr;
    const __half* p = g_preh + (size_t)row * D_HID;
    for (int i = t; i < D_HID; i += 256) {
        if (__half2float(p[i]) >= thr) {
            int pos = atomicAdd(&s_cnt, 1);
            if (pos < CAND_MAX) g_ci[(size_t)row * CAND_MAX + pos] = i;
        }
    }
    __syncthreads();
    if (t == 0) g_cn[row] = (s_cnt < CAND_MAX) ? s_cnt : CAND_MAX;
}

// ---------------- rescue: exact fp32 dots (R1-identical order) + top-128 ------
__global__ __launch_bounds__(256, 2) void rescue_kernel(const float* __restrict__ b_enc) {
    extern __shared__ float dyn[];
    float* sx = dyn;                                   // [D_MODEL]
    float* sw = dyn + D_MODEL;                         // [CAND_MAX][RPAD]
    float* sv = sw + CAND_MAX * RPAD;                  // [CAND_MAX]
    int*   si = (int*)(sv + CAND_MAX);                 // [CAND_MAX]

    const int row = blockIdx.x;
    const int t = threadIdx.x;

    #pragma unroll
    for (int q = 0; q < 4; q++)
        sx[t + q * 256] = g_xn[(size_t)row * D_MODEL + t + q * 256];
    si[t] = (t < g_cn[row]) ? g_ci[(size_t)row * CAND_MAX + t] : 0x7FFFFFFF;
    __syncthreads();
    const int C = g_cn[row];
    const int myIdx = si[t];

    float acc = 0.f;
    for (int k0 = 0; k0 < D_MODEL; k0 += RTILE) {
        const int q = t & 15;                // 16 float4 = 64 floats
        #pragma unroll
        for (int pass = 0; pass < 16; pass++) {
            const int c = pass * 16 + (t >> 4);
            if (c < C) {
                const float4 v = *reinterpret_cast<const float4*>(
                    g_bt + (size_t)si[c] * D_MODEL + k0 + q * 4);
                float* dst = sw + c * RPAD + q * 4;
                dst[0] = v.x; dst[1] = v.y; dst[2] = v.z; dst[3] = v.w;
            }
        }
        __syncthreads();
        if (t < C) {
            const float* wrow = sw + t * RPAD;
            #pragma unroll
            for (int kk = 0; kk < RTILE; kk++)
                acc = fmaf(sx[k0 + kk], wrow[kk], acc);   // strict sequential chain
        }
        __syncthreads();
    }

    if (t < C) {
        sv[t] = acc + __ldg(&b_enc[myIdx]);
    } else {
        sv[t] = -__int_as_float(0x7F800000);   // -inf
    }
    __syncthreads();

    // bitonic sort 256: val desc, idx asc (jax tie order)
    #pragma unroll 1
    for (int k = 2; k <= CAND_MAX; k <<= 1) {
        #pragma unroll 1
        for (int j = k >> 1; j > 0; j >>= 1) {
            const int ixj = t ^ j;
            if (ixj > t) {
                float v0 = sv[t], v1 = sv[ixj];
                int i0 = si[t], i1 = si[ixj];
                bool firstWins = (v0 > v1) || (v0 == v1 && i0 < i1);
                if (((t & k) == 0) != firstWins) {
                    sv[t] = v1; sv[ixj] = v0;
                    si[t] = i1; si[ixj] = i0;
                }
            }
            __syncthreads();
        }
    }

    if (t < TOPK) {
        g_tv[(size_t)row * TOPK + t] = fmaxf(sv[t], 0.0f);
        g_ti[(size_t)row * TOPK + t] = si[t];
    }
}

// ---------------- sparse decode + de-normalize -------------------------------
__global__ __launch_bounds__(256) void decode_kernel(const float* __restrict__ w_dec,
                                                     const float* __restrict__ b_pre,
                                                     float* __restrict__ out) {
    __shared__ float sval[TOPK];
    __shared__ int   sidx[TOPK];
    const int row = blockIdx.x;
    const int t = threadIdx.x;
    if (t < TOPK) {
        sval[t] = g_tv[(size_t)row * TOPK + t];
        sidx[t] = g_ti[(size_t)row * TOPK + t];
    }
    __syncthreads();

    float acc0 = 0.f, acc1 = 0.f, acc2 = 0.f, acc3 = 0.f;
    #pragma unroll 4
    for (int j = 0; j < TOPK; j++) {
        const float v = sval[j];
        const float* wr = w_dec + (size_t)sidx[j] * D_MODEL;
        acc0 += v * __ldg(&wr[t]);
        acc1 += v * __ldg(&wr[t + 256]);
        acc2 += v * __ldg(&wr[t + 512]);
        acc3 += v * __ldg(&wr[t + 768]);
    }
    const float m = g_mu[row], s = g_sd[row];
    float* o = out + (size_t)row * D_MODEL;
    o[t]       = (acc0 + b_pre[t])       * s + m;
    o[t + 256] = (acc1 + b_pre[t + 256]) * s + m;
    o[t + 512] = (acc2 + b_pre[t + 512]) * s + m;
    o[t + 768] = (acc3 + b_pre[t + 768]) * s + m;
}

// ---------------- launch ------------------------------------------------------
extern "C" void kernel_launch(void* const* d_in, const int* in_sizes, int n_in,
                              void* d_out, int out_size) {
    const float* x     = (const float*)d_in[0];
    const float* w_enc = (const float*)d_in[1];
    const float* w_dec = (const float*)d_in[2];
    const float* b_enc = (const float*)d_in[3];
    const float* b_pre = (const float*)d_in[4];
    float* out = (float*)d_out;

    // 1. LayerNorm (fp32 out + fp16 copy)
    ln_kernel<<<N_TOK, 256>>>(x, b_pre);

    // 2. Transpose w_enc -> fp32 + fp16(x256) [D_HID, D_MODEL]
    dim3 tg(D_HID / 32, D_MODEL / 32);
    transpose_split<<<tg, dim3(32, 8)>>>(w_enc);

    // 3. Approximate HMMA encoder GEMM (single fp16 product, fp16 output)
    cudaFuncSetAttribute(enc_gemm_mma, cudaFuncAttributeMaxDynamicSharedMemorySize, GEMM_SMEM);
    dim3 ggrid(N_TOK / TM, D_HID / TN);
    enc_gemm_mma<<<ggrid, 256, GEMM_SMEM>>>(b_enc);

    // 4. Histogram-select approx top-128 + margin candidate collection
    topk_kernel<<<N_TOK, 256>>>();

    // 5. Rescue: R1-identical sequential fp32 dots, smem-staged coalesced loads
    cudaFuncSetAttribute(rescue_kernel, cudaFuncAttributeMaxDynamicSharedMemorySize, RES_SMEM);
    rescue_kernel<<<N_TOK, 256, RES_SMEM>>>(b_enc);

    // 6. Sparse decode + un-normalize
    decode_kernel<<<N_TOK, 256>>>(w_dec, b_pre, out);
}